// round 11
// baseline (speedup 1.0000x reference)
#include <cuda_runtime.h>
#include <cstdint>
#include <math.h>

// ---------------- problem constants ----------------
#define ALPHAC 1.702f
#define LIMITC 7.0f
#define NTOK   1024
#define HD     2880
#define NE     16
#define ID     2880
#define TOPK   4
#define NSLOT  (NTOK*TOPK)
#define SLOTPAD (NSLOT+128)

// ---------------- device scratch -------------------------------------------
__device__ int   g_topk_eid[NSLOT];
__device__ float g_topk_prob[NSLOT];
__device__ int   g_expert_off[NE+1];
__device__ int   g_slot_token[SLOTPAD];
__device__ int   g_token_slot[NSLOT];
__device__ float g_act [(size_t)SLOTPAD*ID];
__device__ float g_out2[(size_t)SLOTPAD*HD];

// ---------------- helpers ---------------------------------------------------
__device__ __forceinline__ float to_tf32(float x) {
    float r; asm("cvt.rna.tf32.f32 %0, %1;" : "=f"(r) : "f"(x)); return r;
}
__device__ __forceinline__ void mma_tf32_16n8k8(float* d, const uint32_t* a, const uint32_t* b) {
    asm volatile(
        "mma.sync.aligned.m16n8k8.row.col.f32.tf32.tf32.f32 "
        "{%0,%1,%2,%3}, {%4,%5,%6,%7}, {%8,%9}, {%0,%1,%2,%3};\n"
        : "+f"(d[0]), "+f"(d[1]), "+f"(d[2]), "+f"(d[3])
        : "r"(a[0]), "r"(a[1]), "r"(a[2]), "r"(a[3]), "r"(b[0]), "r"(b[1]));
}
__device__ __forceinline__ void cvt_store4(float* dst, float4 v) {
    v.x = to_tf32(v.x); v.y = to_tf32(v.y); v.z = to_tf32(v.z); v.w = to_tf32(v.w);
    *(float4*)dst = v;
}

// ---------------- 1. router (exact fp32) ------------------------------------
__global__ __launch_bounds__(256) void router_kernel(
    const float* __restrict__ hidden,
    const float* __restrict__ rw,
    const float* __restrict__ rb)
{
    const int t = blockIdx.x;
    const float* __restrict__ x = hidden + (size_t)t * HD;
    const int warp = threadIdx.x >> 5, lane = threadIdx.x & 31;
    __shared__ float logits[NE];

    const int e0 = warp * 2, e1 = e0 + 1;
    const float* __restrict__ w0 = rw + (size_t)e0 * HD;
    const float* __restrict__ w1r = rw + (size_t)e1 * HD;
    float s0 = 0.f, s1 = 0.f;
    for (int k = lane; k < HD; k += 32) {
        float xv = x[k];
        s0 = fmaf(xv, w0[k], s0);
        s1 = fmaf(xv, w1r[k], s1);
    }
    #pragma unroll
    for (int o = 16; o; o >>= 1) {
        s0 += __shfl_xor_sync(0xffffffffu, s0, o);
        s1 += __shfl_xor_sync(0xffffffffu, s1, o);
    }
    if (lane == 0) { logits[e0] = s0 + rb[e0]; logits[e1] = s1 + rb[e1]; }
    __syncthreads();

    if (threadIdx.x == 0) {
        float v[NE];
        #pragma unroll
        for (int e = 0; e < NE; e++) v[e] = logits[e];
        int ids[TOPK]; float vals[TOPK];
        #pragma unroll
        for (int kk = 0; kk < TOPK; kk++) {
            int bi = 0; float bv = -INFINITY;
            #pragma unroll
            for (int e = 0; e < NE; e++)
                if (v[e] > bv) { bv = v[e]; bi = e; }
            ids[kk] = bi; vals[kk] = bv; v[bi] = -INFINITY;
        }
        float m = vals[0], ssum = 0.f, p[TOPK];
        #pragma unroll
        for (int kk = 0; kk < TOPK; kk++) { p[kk] = __expf(vals[kk] - m); ssum += p[kk]; }
        float inv = 1.f / ssum;
        #pragma unroll
        for (int kk = 0; kk < TOPK; kk++) {
            g_topk_eid [t*TOPK + kk] = ids[kk];
            g_topk_prob[t*TOPK + kk] = p[kk] * inv;
        }
    }
}

// ---------------- 2. build per-expert token lists ---------------------------
__global__ __launch_bounds__(512) void build_kernel()
{
    __shared__ int counts[NE];
    __shared__ int offs[NE+1];
    const int warp = threadIdx.x >> 5, lane = threadIdx.x & 31;
    const int e = warp;

    int cnt = 0;
    for (int base = 0; base < NTOK; base += 32) {
        const int t = base + lane;
        bool match = false;
        #pragma unroll
        for (int kk = 0; kk < TOPK; kk++) match |= (g_topk_eid[t*TOPK + kk] == e);
        cnt += __popc(__ballot_sync(0xffffffffu, match));
    }
    if (lane == 0) counts[e] = cnt;
    __syncthreads();
    if (threadIdx.x == 0) {
        int acc = 0;
        for (int i = 0; i < NE; i++) { offs[i] = acc; acc += counts[i]; }
        offs[NE] = acc;
        for (int i = 0; i <= NE; i++) g_expert_off[i] = offs[i];
    }
    __syncthreads();

    int run = offs[e];
    for (int base = 0; base < NTOK; base += 32) {
        const int t = base + lane;
        int kkm = -1;
        #pragma unroll
        for (int kk = 0; kk < TOPK; kk++)
            if (g_topk_eid[t*TOPK + kk] == e) kkm = kk;
        unsigned mask = __ballot_sync(0xffffffffu, kkm >= 0);
        int rank = __popc(mask & ((1u << lane) - 1u));
        if (kkm >= 0) {
            int slot = run + rank;
            g_slot_token[slot] = t;
            g_token_slot[t*TOPK + kkm] = slot;
        }
        run += __popc(mask);
    }
}

// ---------------- shared GEMM geometry --------------------------------------
// BM=128, BN=128, BK=32. 384 threads: warps 0-7 consume (2m x 4n, 64x32 each),
// warps 8-11 produce (LDG -> tf32 cvt -> STS, one chunk ahead).
#define BK      32
#define KSTRIDE 36
#define ASZ     (128*KSTRIDE)
#define SMEM_TC (4*ASZ*4)     // 73728 bytes

// ---------------- 3. GEMM1: gu = X @ w1^T, fused activation -----------------
__global__ __launch_bounds__(384, 1) void gemm1_tc(
    const float* __restrict__ hidden,
    const float* __restrict__ w1,
    const float* __restrict__ b1)
{
    const int e   = blockIdx.z;
    const int off = g_expert_off[e];
    const int cnt = g_expert_off[e+1] - off;
    const int m0  = blockIdx.y * 128;
    if (m0 >= cnt) return;
    const int n0  = blockIdx.x * 128;
    const int tid = threadIdx.x, wid = tid >> 5, lane = tid & 31;

    extern __shared__ float sm[];
    float* Asm = sm;
    float* Bsm = sm + 2*ASZ;

    const int C = HD / BK;   // 90
    const bool is_consumer = (wid < 8);

    if (!is_consumer) {
        // ---------------- producer warps ----------------
        const int pid = tid - 256;          // 0..127 => one row of A and one of B
        int amrow = m0 + pid; if (amrow >= cnt) amrow = cnt - 1;
        const int atok = g_slot_token[off + amrow];
        const float* __restrict__ aptr = hidden + (size_t)atok * HD;
        const float* __restrict__ bptr = w1 + ((size_t)e * 2*ID + (size_t)(n0 + pid)) * HD;
        float* asts = Asm + pid*KSTRIDE;
        float* bsts = Bsm + pid*KSTRIDE;

        // preload chunk 0 into buffer 0
        #pragma unroll
        for (int j = 0; j < 8; j++) cvt_store4(asts + j*4, *(const float4*)(aptr + j*4));
        #pragma unroll
        for (int j = 0; j < 8; j++) cvt_store4(bsts + j*4, *(const float4*)(bptr + j*4));
        __syncthreads();

        for (int c = 0; c < C; c++) {
            if (c + 1 < C) {
                const int k0 = (c + 1) * BK;
                const int nb = (c + 1) & 1;
                float4 av[8], bv[8];
                #pragma unroll
                for (int j = 0; j < 8; j++) av[j] = *(const float4*)(aptr + k0 + j*4);
                #pragma unroll
                for (int j = 0; j < 8; j++) bv[j] = *(const float4*)(bptr + k0 + j*4);
                #pragma unroll
                for (int j = 0; j < 8; j++) cvt_store4(asts + nb*ASZ + j*4, av[j]);
                #pragma unroll
                for (int j = 0; j < 8; j++) cvt_store4(bsts + nb*ASZ + j*4, bv[j]);
            }
            __syncthreads();
        }
        return;   // producers exit; consumers run a barrier-free epilogue
    }

    // ---------------- consumer warps ----------------
    const int wm = wid & 1, wn = wid >> 1;
    const int lr = lane >> 2, lc = lane & 3;

    float acc[4][4][4];
    #pragma unroll
    for (int i = 0; i < 4; i++)
        #pragma unroll
        for (int j = 0; j < 4; j++)
            #pragma unroll
            for (int q = 0; q < 4; q++) acc[i][j][q] = 0.f;

    __syncthreads();   // matches producers' preload barrier

    for (int c = 0; c < C; c++) {
        const int buf = c & 1;
        const float* A = Asm + buf*ASZ;
        const float* B = Bsm + buf*ASZ;
        #pragma unroll
        for (int ks = 0; ks < 4; ks++) {
            uint32_t af[4][4], bf[4][2];
            #pragma unroll
            for (int mt = 0; mt < 4; mt++) {
                const float* p = A + (wm*64 + mt*16 + lr)*KSTRIDE + ks*8 + lc;
                af[mt][0] = __float_as_uint(p[0]);
                af[mt][1] = __float_as_uint(p[8*KSTRIDE]);
                af[mt][2] = __float_as_uint(p[4]);
                af[mt][3] = __float_as_uint(p[8*KSTRIDE + 4]);
            }
            #pragma unroll
            for (int nt = 0; nt < 4; nt++) {
                const float* p = B + (wn*32 + nt*8 + lr)*KSTRIDE + ks*8 + lc;
                bf[nt][0] = __float_as_uint(p[0]);
                bf[nt][1] = __float_as_uint(p[4]);
            }
            #pragma unroll
            for (int mt = 0; mt < 4; mt++)
                #pragma unroll
                for (int nt = 0; nt < 4; nt++)
                    mma_tf32_16n8k8(acc[mt][nt], af[mt], bf[nt]);
        }
        __syncthreads();
    }

    // epilogue: c0/c1 adjacent even/odd columns = (gate, up)
    const float* __restrict__ b1e = b1 + (size_t)e * 2*ID;
    #pragma unroll
    for (int mt = 0; mt < 4; mt++) {
        const int mrow0 = m0 + wm*64 + mt*16 + lr;
        #pragma unroll
        for (int half = 0; half < 2; half++) {
            const int m = mrow0 + half*8;
            if (m >= cnt) continue;
            float* __restrict__ arow = g_act + (size_t)(off + m) * ID;
            #pragma unroll
            for (int nt = 0; nt < 4; nt++) {
                const int ng = n0 + wn*32 + nt*8 + lc*2;
                float g = acc[mt][nt][2*half]     + b1e[ng];
                float u = acc[mt][nt][2*half + 1] + b1e[ng + 1];
                g = fminf(g, LIMITC);
                u = fminf(fmaxf(u, -LIMITC), LIMITC);
                float sig = 1.f / (1.f + __expf(-ALPHAC * g));
                arow[ng >> 1] = (u + 1.f) * (g * sig);
            }
        }
    }
}

// ---------------- 4. GEMM2: out_e = act @ w2^T + b2 -------------------------
__global__ __launch_bounds__(384, 1) void gemm2_tc(
    const float* __restrict__ w2,
    const float* __restrict__ b2)
{
    const int e   = blockIdx.z;
    const int off = g_expert_off[e];
    const int cnt = g_expert_off[e+1] - off;
    const int m0  = blockIdx.y * 128;
    if (m0 >= cnt) return;
    const int n0  = blockIdx.x * 128;
    const int tid = threadIdx.x, wid = tid >> 5, lane = tid & 31;

    extern __shared__ float sm[];
    float* Asm = sm;
    float* Bsm = sm + 2*ASZ;

    const int C = ID / BK;   // 90
    const bool is_consumer = (wid < 8);

    if (!is_consumer) {
        const int pid = tid - 256;
        int amrow = m0 + pid; if (amrow >= cnt) amrow = cnt - 1;
        int bnrow = n0 + pid; if (bnrow >= HD)  bnrow = HD - 1;
        const float* __restrict__ aptr = g_act + (size_t)(off + amrow) * ID;
        const float* __restrict__ bptr = w2 + ((size_t)e * HD + (size_t)bnrow) * ID;
        float* asts = Asm + pid*KSTRIDE;
        float* bsts = Bsm + pid*KSTRIDE;

        #pragma unroll
        for (int j = 0; j < 8; j++) cvt_store4(asts + j*4, *(const float4*)(aptr + j*4));
        #pragma unroll
        for (int j = 0; j < 8; j++) cvt_store4(bsts + j*4, *(const float4*)(bptr + j*4));
        __syncthreads();

        for (int c = 0; c < C; c++) {
            if (c + 1 < C) {
                const int k0 = (c + 1) * BK;
                const int nb = (c + 1) & 1;
                float4 av[8], bv[8];
                #pragma unroll
                for (int j = 0; j < 8; j++) av[j] = *(const float4*)(aptr + k0 + j*4);
                #pragma unroll
                for (int j = 0; j < 8; j++) bv[j] = *(const float4*)(bptr + k0 + j*4);
                #pragma unroll
                for (int j = 0; j < 8; j++) cvt_store4(asts + nb*ASZ + j*4, av[j]);
                #pragma unroll
                for (int j = 0; j < 8; j++) cvt_store4(bsts + nb*ASZ + j*4, bv[j]);
            }
            __syncthreads();
        }
        return;
    }

    const int wm = wid & 1, wn = wid >> 1;
    const int lr = lane >> 2, lc = lane & 3;

    float acc[4][4][4];
    #pragma unroll
    for (int i = 0; i < 4; i++)
        #pragma unroll
        for (int j = 0; j < 4; j++)
            #pragma unroll
            for (int q = 0; q < 4; q++) acc[i][j][q] = 0.f;

    __syncthreads();

    for (int c = 0; c < C; c++) {
        const int buf = c & 1;
        const float* A = Asm + buf*ASZ;
        const float* B = Bsm + buf*ASZ;
        #pragma unroll
        for (int ks = 0; ks < 4; ks++) {
            uint32_t af[4][4], bf[4][2];
            #pragma unroll
            for (int mt = 0; mt < 4; mt++) {
                const float* p = A + (wm*64 + mt*16 + lr)*KSTRIDE + ks*8 + lc;
                af[mt][0] = __float_as_uint(p[0]);
                af[mt][1] = __float_as_uint(p[8*KSTRIDE]);
                af[mt][2] = __float_as_uint(p[4]);
                af[mt][3] = __float_as_uint(p[8*KSTRIDE + 4]);
            }
            #pragma unroll
            for (int nt = 0; nt < 4; nt++) {
                const float* p = B + (wn*32 + nt*8 + lr)*KSTRIDE + ks*8 + lc;
                bf[nt][0] = __float_as_uint(p[0]);
                bf[nt][1] = __float_as_uint(p[4]);
            }
            #pragma unroll
            for (int mt = 0; mt < 4; mt++)
                #pragma unroll
                for (int nt = 0; nt < 4; nt++)
                    mma_tf32_16n8k8(acc[mt][nt], af[mt], bf[nt]);
        }
        __syncthreads();
    }

    const float* __restrict__ b2e = b2 + (size_t)e * HD;
    #pragma unroll
    for (int mt = 0; mt < 4; mt++) {
        const int mrow0 = m0 + wm*64 + mt*16 + lr;
        #pragma unroll
        for (int half = 0; half < 2; half++) {
            const int m = mrow0 + half*8;
            if (m >= cnt) continue;
            float* __restrict__ orow = g_out2 + (size_t)(off + m) * HD;
            #pragma unroll
            for (int nt = 0; nt < 4; nt++) {
                const int n = n0 + wn*32 + nt*8 + lc*2;
                if (n < HD) {
                    orow[n]     = acc[mt][nt][2*half]     + b2e[n];
                    orow[n + 1] = acc[mt][nt][2*half + 1] + b2e[n + 1];
                }
            }
        }
    }
}

// ---------------- 5. combine ------------------------------------------------
__global__ __launch_bounds__(256) void combine_kernel(float* __restrict__ out)
{
    const int t = blockIdx.x;
    __shared__ int   ss[TOPK];
    __shared__ float pp[TOPK];
    if (threadIdx.x < TOPK) {
        ss[threadIdx.x] = g_token_slot[t*TOPK + threadIdx.x];
        pp[threadIdx.x] = g_topk_prob[t*TOPK + threadIdx.x];
    }
    __syncthreads();
    const int   s0 = ss[0], s1 = ss[1], s2 = ss[2], s3 = ss[3];
    const float p0 = pp[0], p1 = pp[1], p2 = pp[2], p3 = pp[3];
    const float* __restrict__ r0 = g_out2 + (size_t)s0 * HD;
    const float* __restrict__ r1 = g_out2 + (size_t)s1 * HD;
    const float* __restrict__ r2 = g_out2 + (size_t)s2 * HD;
    const float* __restrict__ r3 = g_out2 + (size_t)s3 * HD;
    float* __restrict__ o = out + (size_t)t * HD;
    for (int h = threadIdx.x; h < HD; h += blockDim.x) {
        o[h] = p0*r0[h] + p1*r1[h] + p2*r2[h] + p3*r3[h];
    }
}

// ---------------- launch ----------------------------------------------------
extern "C" void kernel_launch(void* const* d_in, const int* in_sizes, int n_in,
                              void* d_out, int out_size)
{
    const float* hidden   = (const float*)d_in[0];
    const float* router_w = (const float*)d_in[1];
    const float* router_b = (const float*)d_in[2];
    const float* w1       = (const float*)d_in[3];
    const float* b1       = (const float*)d_in[4];
    const float* w2       = (const float*)d_in[5];
    const float* b2       = (const float*)d_in[6];
    float* out = (float*)d_out;

    cudaFuncSetAttribute(gemm1_tc, cudaFuncAttributeMaxDynamicSharedMemorySize, SMEM_TC);
    cudaFuncSetAttribute(gemm2_tc, cudaFuncAttributeMaxDynamicSharedMemorySize, SMEM_TC);

    router_kernel<<<NTOK, 256>>>(hidden, router_w, router_b);
    build_kernel<<<1, 512>>>();
    gemm1_tc<<<dim3(45, 8, NE), 384, SMEM_TC>>>(hidden, w1, b1);
    gemm2_tc<<<dim3(23, 8, NE), 384, SMEM_TC>>>(w2, b2);
    combine_kernel<<<NTOK, 256>>>(out);
}

// round 14
// speedup vs baseline: 1.5024x; 1.5024x over previous
#include <cuda_runtime.h>
#include <cstdint>
#include <math.h>

// ---------------- problem constants ----------------
#define ALPHAC 1.702f
#define LIMITC 7.0f
#define NTOK   1024
#define HD     2880
#define NE     16
#define ID     2880
#define TOPK   4
#define NSLOT  (NTOK*TOPK)
#define SLOTPAD (NSLOT+128)

// ---------------- device scratch -------------------------------------------
__device__ int   g_topk_eid[NSLOT];
__device__ float g_topk_prob[NSLOT];
__device__ int   g_expert_off[NE+1];
__device__ int   g_slot_token[SLOTPAD];
__device__ int   g_token_slot[NSLOT];
__device__ float g_act [(size_t)SLOTPAD*ID];
__device__ float g_out2[(size_t)SLOTPAD*HD];

// ---------------- helpers ---------------------------------------------------
__device__ __forceinline__ float to_tf32(float x) {
    float r; asm("cvt.rna.tf32.f32 %0, %1;" : "=f"(r) : "f"(x)); return r;
}
__device__ __forceinline__ void mma_tf32_16n8k8(float* d, const uint32_t* a, const uint32_t* b) {
    asm volatile(
        "mma.sync.aligned.m16n8k8.row.col.f32.tf32.tf32.f32 "
        "{%0,%1,%2,%3}, {%4,%5,%6,%7}, {%8,%9}, {%0,%1,%2,%3};\n"
        : "+f"(d[0]), "+f"(d[1]), "+f"(d[2]), "+f"(d[3])
        : "r"(a[0]), "r"(a[1]), "r"(a[2]), "r"(a[3]), "r"(b[0]), "r"(b[1]));
}
// pair-permuted store of 8 k-values: positions (2j, 2j+1) hold (k=j, k=j+4)
__device__ __forceinline__ void perm_store8(float* dst, float4 v0, float4 v1) {
    float4 p0 = make_float4(to_tf32(v0.x), to_tf32(v1.x), to_tf32(v0.y), to_tf32(v1.y));
    float4 p1 = make_float4(to_tf32(v0.z), to_tf32(v1.z), to_tf32(v0.w), to_tf32(v1.w));
    *(float4*)dst       = p0;
    *(float4*)(dst + 4) = p1;
}

// ---------------- 1. router (exact fp32) ------------------------------------
__global__ __launch_bounds__(256) void router_kernel(
    const float* __restrict__ hidden,
    const float* __restrict__ rw,
    const float* __restrict__ rb)
{
    const int t = blockIdx.x;
    const float* __restrict__ x = hidden + (size_t)t * HD;
    const int warp = threadIdx.x >> 5, lane = threadIdx.x & 31;
    __shared__ float logits[NE];

    const int e0 = warp * 2, e1 = e0 + 1;
    const float* __restrict__ w0 = rw + (size_t)e0 * HD;
    const float* __restrict__ w1r = rw + (size_t)e1 * HD;
    float s0 = 0.f, s1 = 0.f;
    for (int k = lane; k < HD; k += 32) {
        float xv = x[k];
        s0 = fmaf(xv, w0[k], s0);
        s1 = fmaf(xv, w1r[k], s1);
    }
    #pragma unroll
    for (int o = 16; o; o >>= 1) {
        s0 += __shfl_xor_sync(0xffffffffu, s0, o);
        s1 += __shfl_xor_sync(0xffffffffu, s1, o);
    }
    if (lane == 0) { logits[e0] = s0 + rb[e0]; logits[e1] = s1 + rb[e1]; }
    __syncthreads();

    if (threadIdx.x == 0) {
        float v[NE];
        #pragma unroll
        for (int e = 0; e < NE; e++) v[e] = logits[e];
        int ids[TOPK]; float vals[TOPK];
        #pragma unroll
        for (int kk = 0; kk < TOPK; kk++) {
            int bi = 0; float bv = -INFINITY;
            #pragma unroll
            for (int e = 0; e < NE; e++)
                if (v[e] > bv) { bv = v[e]; bi = e; }
            ids[kk] = bi; vals[kk] = bv; v[bi] = -INFINITY;
        }
        float m = vals[0], ssum = 0.f, p[TOPK];
        #pragma unroll
        for (int kk = 0; kk < TOPK; kk++) { p[kk] = __expf(vals[kk] - m); ssum += p[kk]; }
        float inv = 1.f / ssum;
        #pragma unroll
        for (int kk = 0; kk < TOPK; kk++) {
            g_topk_eid [t*TOPK + kk] = ids[kk];
            g_topk_prob[t*TOPK + kk] = p[kk] * inv;
        }
    }
}

// ---------------- 2. build per-expert token lists ---------------------------
__global__ __launch_bounds__(512) void build_kernel()
{
    __shared__ int counts[NE];
    __shared__ int offs[NE+1];
    const int warp = threadIdx.x >> 5, lane = threadIdx.x & 31;
    const int e = warp;

    int cnt = 0;
    for (int base = 0; base < NTOK; base += 32) {
        const int t = base + lane;
        bool match = false;
        #pragma unroll
        for (int kk = 0; kk < TOPK; kk++) match |= (g_topk_eid[t*TOPK + kk] == e);
        cnt += __popc(__ballot_sync(0xffffffffu, match));
    }
    if (lane == 0) counts[e] = cnt;
    __syncthreads();
    if (threadIdx.x == 0) {
        int acc = 0;
        for (int i = 0; i < NE; i++) { offs[i] = acc; acc += counts[i]; }
        offs[NE] = acc;
        for (int i = 0; i <= NE; i++) g_expert_off[i] = offs[i];
    }
    __syncthreads();

    int run = offs[e];
    for (int base = 0; base < NTOK; base += 32) {
        const int t = base + lane;
        int kkm = -1;
        #pragma unroll
        for (int kk = 0; kk < TOPK; kk++)
            if (g_topk_eid[t*TOPK + kk] == e) kkm = kk;
        unsigned mask = __ballot_sync(0xffffffffu, kkm >= 0);
        int rank = __popc(mask & ((1u << lane) - 1u));
        if (kkm >= 0) {
            int slot = run + rank;
            g_slot_token[slot] = t;
            g_token_slot[t*TOPK + kkm] = slot;
        }
        run += __popc(mask);
    }
}

// ---------------- shared GEMM geometry --------------------------------------
// BM=128, BN=128, BK=32. 512 threads = 16 warps in a 4(m) x 4(n) grid,
// warp tile 32x32 (mt=2 x nt=4 m16n8k8 frags). Unified load+compute warps.
// Smem rows use pair-permuted k layout: positions (2j,2j+1) <- (k=j, k=j+4)
// within each 8-wide k-group, enabling LDS.64 fragment loads.
#define BK      32
#define KSTRIDE 40
#define ASZ     (128*KSTRIDE)      // floats per buffer per matrix
#define SMEM_TC (4*ASZ*4)          // 2 bufs x (A+B) = 81920 bytes

// ---------------- 3. GEMM1: gu = X @ w1^T, fused activation -----------------
__global__ __launch_bounds__(512, 1) void gemm1_tc(
    const float* __restrict__ hidden,
    const float* __restrict__ w1,
    const float* __restrict__ b1)
{
    const int e   = blockIdx.z;
    const int off = g_expert_off[e];
    const int cnt = g_expert_off[e+1] - off;
    const int m0  = blockIdx.y * 128;
    if (m0 >= cnt) return;
    const int n0  = blockIdx.x * 128;
    const int tid = threadIdx.x, wid = tid >> 5, lane = tid & 31;
    const int wm = wid & 3, wn = wid >> 2;
    const int lr = lane >> 2, lc = lane & 3;

    extern __shared__ float sm[];
    float* Asm = sm;               // 2 buffers of ASZ
    float* Bsm = sm + 2*ASZ;       // 2 buffers of ASZ

    // loader geometry: each thread owns one 8-wide k-group of one A row + one B row
    const int arow = tid >> 2;     // 0..127
    const int q    = tid & 3;      // k-group within BK
    int amrow = m0 + arow; if (amrow >= cnt) amrow = cnt - 1;
    const int atok = g_slot_token[off + amrow];
    const float* __restrict__ aptr = hidden + (size_t)atok * HD + q*8;
    const float* __restrict__ bptr = w1 + ((size_t)e * 2*ID + (size_t)(n0 + arow)) * HD + q*8;
    float* asts = Asm + arow*KSTRIDE + q*8;
    float* bsts = Bsm + arow*KSTRIDE + q*8;

    float acc[2][4][4];
    #pragma unroll
    for (int i = 0; i < 2; i++)
        #pragma unroll
        for (int j = 0; j < 4; j++)
            #pragma unroll
            for (int qq = 0; qq < 4; qq++) acc[i][j][qq] = 0.f;

    const int C = HD / BK;   // 90

    // preload chunk 0 into buffer 0
    perm_store8(asts, *(const float4*)(aptr), *(const float4*)(aptr + 4));
    perm_store8(bsts, *(const float4*)(bptr), *(const float4*)(bptr + 4));
    __syncthreads();

    for (int c = 0; c < C; c++) {
        const int buf = c & 1;
        float4 av0, av1, bv0, bv1;
        if (c + 1 < C) {
            const int k0 = (c + 1) * BK;
            av0 = *(const float4*)(aptr + k0);
            av1 = *(const float4*)(aptr + k0 + 4);
            bv0 = *(const float4*)(bptr + k0);
            bv1 = *(const float4*)(bptr + k0 + 4);
        }
        const float* A = Asm + buf*ASZ;
        const float* B = Bsm + buf*ASZ;
        #pragma unroll
        for (int ks = 0; ks < 4; ks++) {
            uint32_t af[2][4], bf[4][2];
            #pragma unroll
            for (int mt = 0; mt < 2; mt++) {
                const int row = wm*32 + mt*16 + lr;
                float2 lo = *(const float2*)(A + row*KSTRIDE + ks*8 + 2*lc);
                float2 hi = *(const float2*)(A + (row + 8)*KSTRIDE + ks*8 + 2*lc);
                af[mt][0] = __float_as_uint(lo.x);
                af[mt][1] = __float_as_uint(hi.x);
                af[mt][2] = __float_as_uint(lo.y);
                af[mt][3] = __float_as_uint(hi.y);
            }
            #pragma unroll
            for (int nt = 0; nt < 4; nt++) {
                const int nrow = wn*32 + nt*8 + lr;
                float2 bb = *(const float2*)(B + nrow*KSTRIDE + ks*8 + 2*lc);
                bf[nt][0] = __float_as_uint(bb.x);
                bf[nt][1] = __float_as_uint(bb.y);
            }
            #pragma unroll
            for (int mt = 0; mt < 2; mt++)
                #pragma unroll
                for (int nt = 0; nt < 4; nt++)
                    mma_tf32_16n8k8(acc[mt][nt], af[mt], bf[nt]);
        }
        if (c + 1 < C) {
            const int nb = (c + 1) & 1;
            perm_store8(asts + nb*ASZ, av0, av1);
            perm_store8(bsts + nb*ASZ, bv0, bv1);
        }
        __syncthreads();
    }

    // epilogue: c0/c1 adjacent even/odd columns = (gate, up)
    const float* __restrict__ b1e = b1 + (size_t)e * 2*ID;
    #pragma unroll
    for (int mt = 0; mt < 2; mt++) {
        const int mrow0 = m0 + wm*32 + mt*16 + lr;
        #pragma unroll
        for (int half = 0; half < 2; half++) {
            const int m = mrow0 + half*8;
            if (m >= cnt) continue;
            float* __restrict__ arow2 = g_act + (size_t)(off + m) * ID;
            #pragma unroll
            for (int nt = 0; nt < 4; nt++) {
                const int ng = n0 + wn*32 + nt*8 + lc*2;
                float g = acc[mt][nt][2*half]     + b1e[ng];
                float u = acc[mt][nt][2*half + 1] + b1e[ng + 1];
                g = fminf(g, LIMITC);
                u = fminf(fmaxf(u, -LIMITC), LIMITC);
                float sig = 1.f / (1.f + __expf(-ALPHAC * g));
                arow2[ng >> 1] = (u + 1.f) * (g * sig);
            }
        }
    }
}

// ---------------- 4. GEMM2: out_e = act @ w2^T + b2 -------------------------
__global__ __launch_bounds__(512, 1) void gemm2_tc(
    const float* __restrict__ w2,
    const float* __restrict__ b2)
{
    const int e   = blockIdx.z;
    const int off = g_expert_off[e];
    const int cnt = g_expert_off[e+1] - off;
    const int m0  = blockIdx.y * 128;
    if (m0 >= cnt) return;
    const int n0  = blockIdx.x * 128;
    const int tid = threadIdx.x, wid = tid >> 5, lane = tid & 31;
    const int wm = wid & 3, wn = wid >> 2;
    const int lr = lane >> 2, lc = lane & 3;

    extern __shared__ float sm[];
    float* Asm = sm;
    float* Bsm = sm + 2*ASZ;

    const int arow = tid >> 2;
    const int q    = tid & 3;
    int amrow = m0 + arow; if (amrow >= cnt) amrow = cnt - 1;
    int bnrow = n0 + arow; if (bnrow >= HD)  bnrow = HD - 1;
    const float* __restrict__ aptr = g_act + (size_t)(off + amrow) * ID + q*8;
    const float* __restrict__ bptr = w2 + ((size_t)e * HD + (size_t)bnrow) * ID + q*8;
    float* asts = Asm + arow*KSTRIDE + q*8;
    float* bsts = Bsm + arow*KSTRIDE + q*8;

    float acc[2][4][4];
    #pragma unroll
    for (int i = 0; i < 2; i++)
        #pragma unroll
        for (int j = 0; j < 4; j++)
            #pragma unroll
            for (int qq = 0; qq < 4; qq++) acc[i][j][qq] = 0.f;

    const int C = ID / BK;   // 90

    perm_store8(asts, *(const float4*)(aptr), *(const float4*)(aptr + 4));
    perm_store8(bsts, *(const float4*)(bptr), *(const float4*)(bptr + 4));
    __syncthreads();

    for (int c = 0; c < C; c++) {
        const int buf = c & 1;
        float4 av0, av1, bv0, bv1;
        if (c + 1 < C) {
            const int k0 = (c + 1) * BK;
            av0 = *(const float4*)(aptr + k0);
            av1 = *(const float4*)(aptr + k0 + 4);
            bv0 = *(const float4*)(bptr + k0);
            bv1 = *(const float4*)(bptr + k0 + 4);
        }
        const float* A = Asm + buf*ASZ;
        const float* B = Bsm + buf*ASZ;
        #pragma unroll
        for (int ks = 0; ks < 4; ks++) {
            uint32_t af[2][4], bf[4][2];
            #pragma unroll
            for (int mt = 0; mt < 2; mt++) {
                const int row = wm*32 + mt*16 + lr;
                float2 lo = *(const float2*)(A + row*KSTRIDE + ks*8 + 2*lc);
                float2 hi = *(const float2*)(A + (row + 8)*KSTRIDE + ks*8 + 2*lc);
                af[mt][0] = __float_as_uint(lo.x);
                af[mt][1] = __float_as_uint(hi.x);
                af[mt][2] = __float_as_uint(lo.y);
                af[mt][3] = __float_as_uint(hi.y);
            }
            #pragma unroll
            for (int nt = 0; nt < 4; nt++) {
                const int nrow = wn*32 + nt*8 + lr;
                float2 bb = *(const float2*)(B + nrow*KSTRIDE + ks*8 + 2*lc);
                bf[nt][0] = __float_as_uint(bb.x);
                bf[nt][1] = __float_as_uint(bb.y);
            }
            #pragma unroll
            for (int mt = 0; mt < 2; mt++)
                #pragma unroll
                for (int nt = 0; nt < 4; nt++)
                    mma_tf32_16n8k8(acc[mt][nt], af[mt], bf[nt]);
        }
        if (c + 1 < C) {
            const int nb = (c + 1) & 1;
            perm_store8(asts + nb*ASZ, av0, av1);
            perm_store8(bsts + nb*ASZ, bv0, bv1);
        }
        __syncthreads();
    }

    const float* __restrict__ b2e = b2 + (size_t)e * HD;
    #pragma unroll
    for (int mt = 0; mt < 2; mt++) {
        const int mrow0 = m0 + wm*32 + mt*16 + lr;
        #pragma unroll
        for (int half = 0; half < 2; half++) {
            const int m = mrow0 + half*8;
            if (m >= cnt) continue;
            float* __restrict__ orow = g_out2 + (size_t)(off + m) * HD;
            #pragma unroll
            for (int nt = 0; nt < 4; nt++) {
                const int n = n0 + wn*32 + nt*8 + lc*2;
                if (n < HD) {
                    orow[n]     = acc[mt][nt][2*half]     + b2e[n];
                    orow[n + 1] = acc[mt][nt][2*half + 1] + b2e[n + 1];
                }
            }
        }
    }
}

// ---------------- 5. combine ------------------------------------------------
__global__ __launch_bounds__(256) void combine_kernel(float* __restrict__ out)
{
    const int t = blockIdx.x;
    __shared__ int   ss[TOPK];
    __shared__ float pp[TOPK];
    if (threadIdx.x < TOPK) {
        ss[threadIdx.x] = g_token_slot[t*TOPK + threadIdx.x];
        pp[threadIdx.x] = g_topk_prob[t*TOPK + threadIdx.x];
    }
    __syncthreads();
    const int   s0 = ss[0], s1 = ss[1], s2 = ss[2], s3 = ss[3];
    const float p0 = pp[0], p1 = pp[1], p2 = pp[2], p3 = pp[3];
    const float* __restrict__ r0 = g_out2 + (size_t)s0 * HD;
    const float* __restrict__ r1 = g_out2 + (size_t)s1 * HD;
    const float* __restrict__ r2 = g_out2 + (size_t)s2 * HD;
    const float* __restrict__ r3 = g_out2 + (size_t)s3 * HD;
    float* __restrict__ o = out + (size_t)t * HD;
    for (int h = threadIdx.x; h < HD; h += blockDim.x) {
        o[h] = p0*r0[h] + p1*r1[h] + p2*r2[h] + p3*r3[h];
    }
}

// ---------------- launch ----------------------------------------------------
extern "C" void kernel_launch(void* const* d_in, const int* in_sizes, int n_in,
                              void* d_out, int out_size)
{
    const float* hidden   = (const float*)d_in[0];
    const float* router_w = (const float*)d_in[1];
    const float* router_b = (const float*)d_in[2];
    const float* w1       = (const float*)d_in[3];
    const float* b1       = (const float*)d_in[4];
    const float* w2       = (const float*)d_in[5];
    const float* b2       = (const float*)d_in[6];
    float* out = (float*)d_out;

    cudaFuncSetAttribute(gemm1_tc, cudaFuncAttributeMaxDynamicSharedMemorySize, SMEM_TC);
    cudaFuncSetAttribute(gemm2_tc, cudaFuncAttributeMaxDynamicSharedMemorySize, SMEM_TC);

    router_kernel<<<NTOK, 256>>>(hidden, router_w, router_b);
    build_kernel<<<1, 512>>>();
    gemm1_tc<<<dim3(45, 8, NE), 512, SMEM_TC>>>(hidden, w1, b1);
    gemm2_tc<<<dim3(23, 8, NE), 512, SMEM_TC>>>(w2, b2);
    combine_kernel<<<NTOK, 256>>>(out);
}

// round 17
// speedup vs baseline: 1.7389x; 1.1574x over previous
#include <cuda_runtime.h>
#include <cstdint>
#include <math.h>

// ---------------- problem constants ----------------
#define ALPHAC 1.702f
#define LIMITC 7.0f
#define NTOK   1024
#define HD     2880
#define NE     16
#define ID     2880
#define TOPK   4
#define NSLOT  (NTOK*TOPK)
#define SLOTPAD (NSLOT+128)

// ---------------- device scratch -------------------------------------------
__device__ int   g_topk_eid[NSLOT];
__device__ float g_topk_prob[NSLOT];
__device__ int   g_expert_off[NE+1];
__device__ int   g_slot_token[SLOTPAD];
__device__ int   g_token_slot[NSLOT];
__device__ float g_act [(size_t)SLOTPAD*ID];
__device__ float g_out2[(size_t)SLOTPAD*HD];

// ---------------- helpers ---------------------------------------------------
__device__ __forceinline__ float to_tf32(float x) {
    float r; asm("cvt.rna.tf32.f32 %0, %1;" : "=f"(r) : "f"(x)); return r;
}
__device__ __forceinline__ void mma_tf32_16n8k8(float* d, const uint32_t* a, const uint32_t* b) {
    asm volatile(
        "mma.sync.aligned.m16n8k8.row.col.f32.tf32.tf32.f32 "
        "{%0,%1,%2,%3}, {%4,%5,%6,%7}, {%8,%9}, {%0,%1,%2,%3};\n"
        : "+f"(d[0]), "+f"(d[1]), "+f"(d[2]), "+f"(d[3])
        : "r"(a[0]), "r"(a[1]), "r"(a[2]), "r"(a[3]), "r"(b[0]), "r"(b[1]));
}
// pair-permuted store of 8 k-values: positions (2j, 2j+1) hold (k=j, k=j+4)
__device__ __forceinline__ void perm_store8(float* dst, float4 v0, float4 v1) {
    float4 p0 = make_float4(to_tf32(v0.x), to_tf32(v1.x), to_tf32(v0.y), to_tf32(v1.y));
    float4 p1 = make_float4(to_tf32(v0.z), to_tf32(v1.z), to_tf32(v0.w), to_tf32(v1.w));
    *(float4*)dst       = p0;
    *(float4*)(dst + 4) = p1;
}

// ---------------- 1. router (exact fp32) ------------------------------------
__global__ __launch_bounds__(256) void router_kernel(
    const float* __restrict__ hidden,
    const float* __restrict__ rw,
    const float* __restrict__ rb)
{
    const int t = blockIdx.x;
    const float* __restrict__ x = hidden + (size_t)t * HD;
    const int warp = threadIdx.x >> 5, lane = threadIdx.x & 31;
    __shared__ float logits[NE];

    const int e0 = warp * 2, e1 = e0 + 1;
    const float* __restrict__ w0 = rw + (size_t)e0 * HD;
    const float* __restrict__ w1r = rw + (size_t)e1 * HD;
    float s0 = 0.f, s1 = 0.f;
    for (int k = lane; k < HD; k += 32) {
        float xv = x[k];
        s0 = fmaf(xv, w0[k], s0);
        s1 = fmaf(xv, w1r[k], s1);
    }
    #pragma unroll
    for (int o = 16; o; o >>= 1) {
        s0 += __shfl_xor_sync(0xffffffffu, s0, o);
        s1 += __shfl_xor_sync(0xffffffffu, s1, o);
    }
    if (lane == 0) { logits[e0] = s0 + rb[e0]; logits[e1] = s1 + rb[e1]; }
    __syncthreads();

    if (threadIdx.x == 0) {
        float v[NE];
        #pragma unroll
        for (int e = 0; e < NE; e++) v[e] = logits[e];
        int ids[TOPK]; float vals[TOPK];
        #pragma unroll
        for (int kk = 0; kk < TOPK; kk++) {
            int bi = 0; float bv = -INFINITY;
            #pragma unroll
            for (int e = 0; e < NE; e++)
                if (v[e] > bv) { bv = v[e]; bi = e; }
            ids[kk] = bi; vals[kk] = bv; v[bi] = -INFINITY;
        }
        float m = vals[0], ssum = 0.f, p[TOPK];
        #pragma unroll
        for (int kk = 0; kk < TOPK; kk++) { p[kk] = __expf(vals[kk] - m); ssum += p[kk]; }
        float inv = 1.f / ssum;
        #pragma unroll
        for (int kk = 0; kk < TOPK; kk++) {
            g_topk_eid [t*TOPK + kk] = ids[kk];
            g_topk_prob[t*TOPK + kk] = p[kk] * inv;
        }
    }
}

// ---------------- 2. build per-expert token lists ---------------------------
__global__ __launch_bounds__(512) void build_kernel()
{
    __shared__ int counts[NE];
    __shared__ int offs[NE+1];
    const int warp = threadIdx.x >> 5, lane = threadIdx.x & 31;
    const int e = warp;

    int cnt = 0;
    for (int base = 0; base < NTOK; base += 32) {
        const int t = base + lane;
        bool match = false;
        #pragma unroll
        for (int kk = 0; kk < TOPK; kk++) match |= (g_topk_eid[t*TOPK + kk] == e);
        cnt += __popc(__ballot_sync(0xffffffffu, match));
    }
    if (lane == 0) counts[e] = cnt;
    __syncthreads();
    if (threadIdx.x == 0) {
        int acc = 0;
        for (int i = 0; i < NE; i++) { offs[i] = acc; acc += counts[i]; }
        offs[NE] = acc;
        for (int i = 0; i <= NE; i++) g_expert_off[i] = offs[i];
    }
    __syncthreads();

    int run = offs[e];
    for (int base = 0; base < NTOK; base += 32) {
        const int t = base + lane;
        int kkm = -1;
        #pragma unroll
        for (int kk = 0; kk < TOPK; kk++)
            if (g_topk_eid[t*TOPK + kk] == e) kkm = kk;
        unsigned mask = __ballot_sync(0xffffffffu, kkm >= 0);
        int rank = __popc(mask & ((1u << lane) - 1u));
        if (kkm >= 0) {
            int slot = run + rank;
            g_slot_token[slot] = t;
            g_token_slot[t*TOPK + kkm] = slot;
        }
        run += __popc(mask);
    }
}

// ---------------- shared GEMM geometry --------------------------------------
// BM=128, BN=192, BK=32. 384 threads = 12 warps in a 2(m) x 6(n) grid,
// warp tile 64x32 (4 mt x 4 nt m16n8k8 frags, 64-reg accumulator).
// Pair-permuted smem rows: positions (2j,2j+1) <- (k=j, k=j+4) per 8-wide
// k-group -> LDS.64 fragment loads, conflict-free at KSTRIDE=40.
// Loaders: 1280 row-slots (A:512, B:768) over 384 threads (<=4 each).
#define BK      32
#define KSTRIDE 40
#define ASZ_A   (128*KSTRIDE)          // 5120 floats per A buffer
#define ASZ_B   (192*KSTRIDE)          // 7680 floats per B buffer
#define SMEM_TC (2*(ASZ_A+ASZ_B)*4)    // 102400 bytes
#define NTHR    384
#define NSLOTS  1280                   // 512 A + 768 B

// ---------------- 3. GEMM1: gu = X @ w1^T, fused activation -----------------
__global__ __launch_bounds__(NTHR, 1) void gemm1_tc(
    const float* __restrict__ hidden,
    const float* __restrict__ w1,
    const float* __restrict__ b1)
{
    const int e   = blockIdx.z;
    const int off = g_expert_off[e];
    const int cnt = g_expert_off[e+1] - off;
    const int m0  = blockIdx.y * 128;
    if (m0 >= cnt) return;
    const int n0  = blockIdx.x * 192;
    const int tid = threadIdx.x, wid = tid >> 5, lane = tid & 31;
    const int wm = wid / 6, wn = wid % 6;
    const int lr = lane >> 2, lc = lane & 3;

    extern __shared__ float sm[];
    float* Asm = sm;                    // 2 buffers of ASZ_A
    float* Bsm = sm + 2*ASZ_A;          // 2 buffers of ASZ_B

    // ---- loader slot setup (A rows then B rows, 4 k-groups each) ----
    const float* gp[4]; float* sp[4]; int bstr[4]; bool val[4];
    #pragma unroll
    for (int i = 0; i < 4; i++) {
        int s = tid + i*NTHR;
        val[i] = (s < NSLOTS);
        int ss = val[i] ? s : 0;
        if (ss < 512) {
            int row = ss >> 2, q = ss & 3;
            int amrow = m0 + row; if (amrow >= cnt) amrow = cnt - 1;
            int tok = g_slot_token[off + amrow];
            gp[i]  = hidden + (size_t)tok * HD + q*8;
            sp[i]  = Asm + row*KSTRIDE + q*8;
            bstr[i] = ASZ_A;
        } else {
            int sb = ss - 512;
            int row = sb >> 2, q = sb & 3;
            gp[i]  = w1 + ((size_t)e * 2*ID + (size_t)(n0 + row)) * HD + q*8;
            sp[i]  = Bsm + row*KSTRIDE + q*8;
            bstr[i] = ASZ_B;
        }
    }

    float acc[4][4][4];
    #pragma unroll
    for (int i = 0; i < 4; i++)
        #pragma unroll
        for (int j = 0; j < 4; j++)
            #pragma unroll
            for (int qq = 0; qq < 4; qq++) acc[i][j][qq] = 0.f;

    const int C = HD / BK;   // 90

    // preload chunk 0 into buffer 0
    #pragma unroll
    for (int i = 0; i < 4; i++)
        if (val[i]) perm_store8(sp[i], *(const float4*)(gp[i]), *(const float4*)(gp[i] + 4));
    __syncthreads();

    for (int c = 0; c < C; c++) {
        const int buf = c & 1;
        float4 pv0[4], pv1[4];
        if (c + 1 < C) {
            const int k0 = (c + 1) * BK;
            #pragma unroll
            for (int i = 0; i < 4; i++) {
                if (val[i]) {
                    pv0[i] = *(const float4*)(gp[i] + k0);
                    pv1[i] = *(const float4*)(gp[i] + k0 + 4);
                }
            }
        }
        const float* A = Asm + buf*ASZ_A;
        const float* B = Bsm + buf*ASZ_B;
        #pragma unroll
        for (int ks = 0; ks < 4; ks++) {
            uint32_t af[4][4], bf[4][2];
            #pragma unroll
            for (int mt = 0; mt < 4; mt++) {
                const int row = wm*64 + mt*16 + lr;
                float2 lo = *(const float2*)(A + row*KSTRIDE + ks*8 + 2*lc);
                float2 hi = *(const float2*)(A + (row + 8)*KSTRIDE + ks*8 + 2*lc);
                af[mt][0] = __float_as_uint(lo.x);
                af[mt][1] = __float_as_uint(hi.x);
                af[mt][2] = __float_as_uint(lo.y);
                af[mt][3] = __float_as_uint(hi.y);
            }
            #pragma unroll
            for (int nt = 0; nt < 4; nt++) {
                const int nrow = wn*32 + nt*8 + lr;
                float2 bb = *(const float2*)(B + nrow*KSTRIDE + ks*8 + 2*lc);
                bf[nt][0] = __float_as_uint(bb.x);
                bf[nt][1] = __float_as_uint(bb.y);
            }
            #pragma unroll
            for (int mt = 0; mt < 4; mt++)
                #pragma unroll
                for (int nt = 0; nt < 4; nt++)
                    mma_tf32_16n8k8(acc[mt][nt], af[mt], bf[nt]);
        }
        if (c + 1 < C) {
            const int nb = (c + 1) & 1;
            #pragma unroll
            for (int i = 0; i < 4; i++)
                if (val[i]) perm_store8(sp[i] + nb*bstr[i], pv0[i], pv1[i]);
        }
        __syncthreads();
    }

    // epilogue: c0/c1 adjacent even/odd columns = (gate, up); 192 | 5760 so no col guard
    const float* __restrict__ b1e = b1 + (size_t)e * 2*ID;
    #pragma unroll
    for (int mt = 0; mt < 4; mt++) {
        const int mrow0 = m0 + wm*64 + mt*16 + lr;
        #pragma unroll
        for (int half = 0; half < 2; half++) {
            const int m = mrow0 + half*8;
            if (m >= cnt) continue;
            float* __restrict__ arow2 = g_act + (size_t)(off + m) * ID;
            #pragma unroll
            for (int nt = 0; nt < 4; nt++) {
                const int ng = n0 + wn*32 + nt*8 + lc*2;
                float g = acc[mt][nt][2*half]     + b1e[ng];
                float u = acc[mt][nt][2*half + 1] + b1e[ng + 1];
                g = fminf(g, LIMITC);
                u = fminf(fmaxf(u, -LIMITC), LIMITC);
                float sig = 1.f / (1.f + __expf(-ALPHAC * g));
                arow2[ng >> 1] = (u + 1.f) * (g * sig);
            }
        }
    }
}

// ---------------- 4. GEMM2: out_e = act @ w2^T + b2 -------------------------
__global__ __launch_bounds__(NTHR, 1) void gemm2_tc(
    const float* __restrict__ w2,
    const float* __restrict__ b2)
{
    const int e   = blockIdx.z;
    const int off = g_expert_off[e];
    const int cnt = g_expert_off[e+1] - off;
    const int m0  = blockIdx.y * 128;
    if (m0 >= cnt) return;
    const int n0  = blockIdx.x * 192;
    const int tid = threadIdx.x, wid = tid >> 5, lane = tid & 31;
    const int wm = wid / 6, wn = wid % 6;
    const int lr = lane >> 2, lc = lane & 3;

    extern __shared__ float sm[];
    float* Asm = sm;
    float* Bsm = sm + 2*ASZ_A;

    const float* gp[4]; float* sp[4]; int bstr[4]; bool val[4];
    #pragma unroll
    for (int i = 0; i < 4; i++) {
        int s = tid + i*NTHR;
        val[i] = (s < NSLOTS);
        int ss = val[i] ? s : 0;
        if (ss < 512) {
            int row = ss >> 2, q = ss & 3;
            int amrow = m0 + row; if (amrow >= cnt) amrow = cnt - 1;
            gp[i]  = g_act + (size_t)(off + amrow) * ID + q*8;
            sp[i]  = Asm + row*KSTRIDE + q*8;
            bstr[i] = ASZ_A;
        } else {
            int sb = ss - 512;
            int row = sb >> 2, q = sb & 3;
            gp[i]  = w2 + ((size_t)e * HD + (size_t)(n0 + row)) * ID + q*8;
            sp[i]  = Bsm + row*KSTRIDE + q*8;
            bstr[i] = ASZ_B;
        }
    }

    float acc[4][4][4];
    #pragma unroll
    for (int i = 0; i < 4; i++)
        #pragma unroll
        for (int j = 0; j < 4; j++)
            #pragma unroll
            for (int qq = 0; qq < 4; qq++) acc[i][j][qq] = 0.f;

    const int C = ID / BK;   // 90

    #pragma unroll
    for (int i = 0; i < 4; i++)
        if (val[i]) perm_store8(sp[i], *(const float4*)(gp[i]), *(const float4*)(gp[i] + 4));
    __syncthreads();

    for (int c = 0; c < C; c++) {
        const int buf = c & 1;
        float4 pv0[4], pv1[4];
        if (c + 1 < C) {
            const int k0 = (c + 1) * BK;
            #pragma unroll
            for (int i = 0; i < 4; i++) {
                if (val[i]) {
                    pv0[i] = *(const float4*)(gp[i] + k0);
                    pv1[i] = *(const float4*)(gp[i] + k0 + 4);
                }
            }
        }
        const float* A = Asm + buf*ASZ_A;
        const float* B = Bsm + buf*ASZ_B;
        #pragma unroll
        for (int ks = 0; ks < 4; ks++) {
            uint32_t af[4][4], bf[4][2];
            #pragma unroll
            for (int mt = 0; mt < 4; mt++) {
                const int row = wm*64 + mt*16 + lr;
                float2 lo = *(const float2*)(A + row*KSTRIDE + ks*8 + 2*lc);
                float2 hi = *(const float2*)(A + (row + 8)*KSTRIDE + ks*8 + 2*lc);
                af[mt][0] = __float_as_uint(lo.x);
                af[mt][1] = __float_as_uint(hi.x);
                af[mt][2] = __float_as_uint(lo.y);
                af[mt][3] = __float_as_uint(hi.y);
            }
            #pragma unroll
            for (int nt = 0; nt < 4; nt++) {
                const int nrow = wn*32 + nt*8 + lr;
                float2 bb = *(const float2*)(B + nrow*KSTRIDE + ks*8 + 2*lc);
                bf[nt][0] = __float_as_uint(bb.x);
                bf[nt][1] = __float_as_uint(bb.y);
            }
            #pragma unroll
            for (int mt = 0; mt < 4; mt++)
                #pragma unroll
                for (int nt = 0; nt < 4; nt++)
                    mma_tf32_16n8k8(acc[mt][nt], af[mt], bf[nt]);
        }
        if (c + 1 < C) {
            const int nb = (c + 1) & 1;
            #pragma unroll
            for (int i = 0; i < 4; i++)
                if (val[i]) perm_store8(sp[i] + nb*bstr[i], pv0[i], pv1[i]);
        }
        __syncthreads();
    }

    // epilogue: 192 | 2880 so no col guard
    const float* __restrict__ b2e = b2 + (size_t)e * HD;
    #pragma unroll
    for (int mt = 0; mt < 4; mt++) {
        const int mrow0 = m0 + wm*64 + mt*16 + lr;
        #pragma unroll
        for (int half = 0; half < 2; half++) {
            const int m = mrow0 + half*8;
            if (m >= cnt) continue;
            float* __restrict__ orow = g_out2 + (size_t)(off + m) * HD;
            #pragma unroll
            for (int nt = 0; nt < 4; nt++) {
                const int n = n0 + wn*32 + nt*8 + lc*2;
                orow[n]     = acc[mt][nt][2*half]     + b2e[n];
                orow[n + 1] = acc[mt][nt][2*half + 1] + b2e[n + 1];
            }
        }
    }
}

// ---------------- 5. combine ------------------------------------------------
__global__ __launch_bounds__(256) void combine_kernel(float* __restrict__ out)
{
    const int t = blockIdx.x;
    __shared__ int   ss[TOPK];
    __shared__ float pp[TOPK];
    if (threadIdx.x < TOPK) {
        ss[threadIdx.x] = g_token_slot[t*TOPK + threadIdx.x];
        pp[threadIdx.x] = g_topk_prob[t*TOPK + threadIdx.x];
    }
    __syncthreads();
    const int   s0 = ss[0], s1 = ss[1], s2 = ss[2], s3 = ss[3];
    const float p0 = pp[0], p1 = pp[1], p2 = pp[2], p3 = pp[3];
    const float* __restrict__ r0 = g_out2 + (size_t)s0 * HD;
    const float* __restrict__ r1 = g_out2 + (size_t)s1 * HD;
    const float* __restrict__ r2 = g_out2 + (size_t)s2 * HD;
    const float* __restrict__ r3 = g_out2 + (size_t)s3 * HD;
    float* __restrict__ o = out + (size_t)t * HD;
    for (int h = threadIdx.x; h < HD; h += blockDim.x) {
        o[h] = p0*r0[h] + p1*r1[h] + p2*r2[h] + p3*r3[h];
    }
}

// ---------------- launch ----------------------------------------------------
extern "C" void kernel_launch(void* const* d_in, const int* in_sizes, int n_in,
                              void* d_out, int out_size)
{
    const float* hidden   = (const float*)d_in[0];
    const float* router_w = (const float*)d_in[1];
    const float* router_b = (const float*)d_in[2];
    const float* w1       = (const float*)d_in[3];
    const float* b1       = (const float*)d_in[4];
    const float* w2       = (const float*)d_in[5];
    const float* b2       = (const float*)d_in[6];
    float* out = (float*)d_out;

    cudaFuncSetAttribute(gemm1_tc, cudaFuncAttributeMaxDynamicSharedMemorySize, SMEM_TC);
    cudaFuncSetAttribute(gemm2_tc, cudaFuncAttributeMaxDynamicSharedMemorySize, SMEM_TC);

    router_kernel<<<NTOK, 256>>>(hidden, router_w, router_b);
    build_kernel<<<1, 512>>>();
    gemm1_tc<<<dim3(30, 8, NE), NTHR, SMEM_TC>>>(hidden, w1, b1);  // 5760/192 = 30
    gemm2_tc<<<dim3(15, 8, NE), NTHR, SMEM_TC>>>(w2, b2);          // 2880/192 = 15
    combine_kernel<<<NTOK, 256>>>(out);
}